// round 2
// baseline (speedup 1.0000x reference)
#include <cuda_runtime.h>
#include <math.h>

// Problem constants
#define T_STEPS 256
#define Bsz     512
#define Dd      512
#define Hh      512
#define NQv     8
#define KIN     1024          // D + H
#define NTOT    2056          // 4*H + NQ
#define ALPHA_C 0.7f

// GEMM tiling
#define BM 64
#define BN 64
#define BK 16

// Scratch (no cudaMalloc allowed) — 16B aligned for float4 access
__device__ __align__(16) float g_Wall[KIN * NTOT];   // packed weights (K-major rows)
__device__ __align__(16) float g_ball[NTOT];         // packed biases
__device__ __align__(16) float g_pre[Bsz * NTOT];    // per-step pre-activations
__device__ __align__(16) float g_hx[Bsz * Hh];
__device__ __align__(16) float g_cx[Bsz * Hh];

__device__ __forceinline__ float sigf(float x) { return 1.0f / (1.0f + expf(-x)); }

// ---------------------------------------------------------------------------
// Pack Wf|Wi|Wu|Wo|Wq -> g_Wall (1024 x 2056), biases -> g_ball, zero state.
// ---------------------------------------------------------------------------
__global__ void pack_kernel(const float* __restrict__ Wf, const float* __restrict__ Wi,
                            const float* __restrict__ Wu, const float* __restrict__ Wo,
                            const float* __restrict__ Wq,
                            const float* __restrict__ bf, const float* __restrict__ bi,
                            const float* __restrict__ bu, const float* __restrict__ bo,
                            const float* __restrict__ bq) {
    int stride = gridDim.x * blockDim.x;
    int idx = blockIdx.x * blockDim.x + threadIdx.x;

    for (int e = idx; e < KIN * NTOT; e += stride) {
        int k = e / NTOT, n = e - k * NTOT;
        float v;
        if (n < 2048) {
            int g = n >> 9, c = n & 511;
            const float* W = (g == 0) ? Wf : (g == 1) ? Wi : (g == 2) ? Wu : Wo;
            v = W[k * 512 + c];
        } else {
            v = Wq[k * NQv + (n - 2048)];
        }
        g_Wall[e] = v;
    }
    if (idx < NTOT) {
        float v;
        if (idx < 2048) {
            int g = idx >> 9, c = idx & 511;
            const float* bb = (g == 0) ? bf : (g == 1) ? bi : (g == 2) ? bu : bo;
            v = bb[c];
        } else {
            v = bq[idx - 2048];
        }
        g_ball[idx] = v;
    }
    for (int e = idx; e < Bsz * Hh; e += stride) {
        g_hx[e] = 0.0f;
        g_cx[e] = 0.0f;
    }
}

// ---------------------------------------------------------------------------
// Per-step GEMM: g_pre = concat(x_t, hx) @ g_Wall + g_ball
//   M = 512 (batch), K = 1024, N = 2056.
//   64x64 block tile, 16 K-slab, 4x4 per thread, 256 threads.
// ---------------------------------------------------------------------------
__global__ __launch_bounds__(256, 2) void gemm_step(const float* __restrict__ xall, int t) {
    __shared__ float As[BK][BM];
    __shared__ float Bs[BK][BN];

    const float* x_t = xall + (size_t)t * Bsz * Dd;

    int tid = threadIdx.x;
    int m0 = blockIdx.y * BM;
    int n0 = blockIdx.x * BN;
    int tm = (tid >> 4) << 2;   // 0..60
    int tn = (tid & 15) << 2;   // 0..60

    float acc[4][4];
#pragma unroll
    for (int i = 0; i < 4; i++)
#pragma unroll
        for (int j = 0; j < 4; j++) acc[i][j] = 0.0f;

    int e = tid * 4;
    int am = e >> 4, ak = e & 15;   // A element block: row am, cols ak..ak+3
    int bk = e >> 6, bn = e & 63;   // B element block: row bk, cols bn..bn+3

    for (int k0 = 0; k0 < KIN; k0 += BK) {
        // Load A slab (concat never straddles the D boundary: BK | D)
        const float* asrc = (k0 < Dd)
            ? (x_t + (size_t)(m0 + am) * Dd + (k0 + ak))
            : (g_hx + (size_t)(m0 + am) * Hh + (k0 - Dd + ak));
        float4 a4 = *reinterpret_cast<const float4*>(asrc);
        As[ak + 0][am] = a4.x;
        As[ak + 1][am] = a4.y;
        As[ak + 2][am] = a4.z;
        As[ak + 3][am] = a4.w;

        // Load B slab
        int gcol = n0 + bn;
        const float* bsrc = g_Wall + (size_t)(k0 + bk) * NTOT + gcol;
        float4 b4;
        if (gcol + 3 < NTOT) {
            b4 = *reinterpret_cast<const float4*>(bsrc);
        } else {
            b4.x = (gcol + 0 < NTOT) ? bsrc[0] : 0.0f;
            b4.y = (gcol + 1 < NTOT) ? bsrc[1] : 0.0f;
            b4.z = (gcol + 2 < NTOT) ? bsrc[2] : 0.0f;
            b4.w = (gcol + 3 < NTOT) ? bsrc[3] : 0.0f;
        }
        *reinterpret_cast<float4*>(&Bs[bk][bn]) = b4;

        __syncthreads();

#pragma unroll
        for (int k = 0; k < BK; ++k) {
            float4 av = *reinterpret_cast<const float4*>(&As[k][tm]);
            float4 bv = *reinterpret_cast<const float4*>(&Bs[k][tn]);
            float a[4] = {av.x, av.y, av.z, av.w};
            float b[4] = {bv.x, bv.y, bv.z, bv.w};
#pragma unroll
            for (int i = 0; i < 4; i++)
#pragma unroll
                for (int j = 0; j < 4; j++)
                    acc[i][j] = fmaf(a[i], b[j], acc[i][j]);
        }
        __syncthreads();
    }

#pragma unroll
    for (int i = 0; i < 4; i++) {
        int gm = m0 + tm + i;
#pragma unroll
        for (int j = 0; j < 4; j++) {
            int gn = n0 + tn + j;
            if (gn < NTOT)
                g_pre[(size_t)gm * NTOT + gn] = acc[i][j] + g_ball[gn];
        }
    }
}

// ---------------------------------------------------------------------------
// Fused pointwise step: quantum cumprod-cosine layers + 8->H projections +
// gate blend + LSTM state update. One block per batch row, one thread per h.
// ---------------------------------------------------------------------------
__global__ __launch_bounds__(512) void point_step(const float* __restrict__ Wqh,
                                                  const float* __restrict__ bqh,
                                                  const float* __restrict__ th_f,
                                                  const float* __restrict__ th_i,
                                                  const float* __restrict__ th_u,
                                                  const float* __restrict__ th_o,
                                                  float* __restrict__ out, int t) {
    int b = blockIdx.x;
    int h = threadIdx.x;

    __shared__ float qv[4][NQv];   // cumprod(cos(q_in + theta_g)) per gate

    if (h < 4) {
        const float* th = (h == 0) ? th_f : (h == 1) ? th_i : (h == 2) ? th_u : th_o;
        const float* qrow = g_pre + (size_t)b * NTOT + 2048;
        float p = 1.0f;
#pragma unroll
        for (int w = 0; w < NQv; ++w) {
            p *= cosf(qrow[w] + th[w]);
            qv[h][w] = p;
        }
    }
    __syncthreads();

    float zf = bqh[h];
    float zi = zf, zu = zf, zo = zf;
#pragma unroll
    for (int w = 0; w < NQv; ++w) {
        float wq = Wqh[w * Hh + h];
        zf = fmaf(qv[0][w], wq, zf);
        zi = fmaf(qv[1][w], wq, zi);
        zu = fmaf(qv[2][w], wq, zu);
        zo = fmaf(qv[3][w], wq, zo);
    }

    const float* prow = g_pre + (size_t)b * NTOT;
    float pf = prow[h];
    float pi = prow[512 + h];
    float pu = prow[1024 + h];
    float po = prow[1536 + h];

    const float A1 = 1.0f - ALPHA_C;
    float f  = ALPHA_C * sigf(pf)  + A1 * sigf(zf);
    float ii = ALPHA_C * sigf(pi)  + A1 * sigf(zi);
    float g  = ALPHA_C * tanhf(pu) + A1 * tanhf(zu);
    float o  = ALPHA_C * sigf(po)  + A1 * sigf(zo);

    size_t idx = (size_t)b * Hh + h;
    float c  = f * g_cx[idx] + ii * g;
    float hv = o * tanhf(c);
    g_cx[idx] = c;
    g_hx[idx] = hv;
    out[(size_t)t * (Bsz * Hh) + idx] = hv;
}

// ---------------------------------------------------------------------------
// Append final (hx, cx) after out[T,B,H].
// ---------------------------------------------------------------------------
__global__ void final_copy(float* __restrict__ dst) {
    int i = blockIdx.x * blockDim.x + threadIdx.x;
    if (i < Bsz * Hh) {
        dst[i] = g_hx[i];
        dst[Bsz * Hh + i] = g_cx[i];
    }
}

extern "C" void kernel_launch(void* const* d_in, const int* in_sizes, int n_in,
                              void* d_out, int out_size) {
    (void)in_sizes; (void)n_in; (void)out_size;
    const float* inputs = (const float*)d_in[0];
    const float* Wf  = (const float*)d_in[1];
    const float* bf  = (const float*)d_in[2];
    const float* Wi  = (const float*)d_in[3];
    const float* bi  = (const float*)d_in[4];
    const float* Wu  = (const float*)d_in[5];
    const float* bu  = (const float*)d_in[6];
    const float* Wo  = (const float*)d_in[7];
    const float* bo  = (const float*)d_in[8];
    const float* Wq  = (const float*)d_in[9];
    const float* bq  = (const float*)d_in[10];
    const float* Wqh = (const float*)d_in[11];
    const float* bqh = (const float*)d_in[12];
    const float* th_f = (const float*)d_in[13];
    const float* th_i = (const float*)d_in[14];
    const float* th_u = (const float*)d_in[15];
    const float* th_o = (const float*)d_in[16];
    float* out = (float*)d_out;

    pack_kernel<<<256, 256>>>(Wf, Wi, Wu, Wo, Wq, bf, bi, bu, bo, bq);

    dim3 ggrid((NTOT + BN - 1) / BN, Bsz / BM);  // 33 x 8
    for (int t = 0; t < T_STEPS; ++t) {
        gemm_step<<<ggrid, 256>>>(inputs, t);
        point_step<<<Bsz, Hh>>>(Wqh, bqh, th_f, th_i, th_u, th_o, out, t);
    }
    final_copy<<<(Bsz * Hh + 255) / 256, 256>>>(out + (size_t)T_STEPS * Bsz * Hh);
}

// round 7
// speedup vs baseline: 1.4429x; 1.4429x over previous
#include <cuda_runtime.h>
#include <math.h>

// Problem constants
#define T_STEPS 256
#define Bsz     512
#define Dd      512
#define Hh      512
#define NQv     8
#define NTOT    2056          // 4*H + NQ
#define NP      2176          // padded to 17*128
#define ALPHA_C 0.7f

// Scratch (no cudaMalloc allowed)
__device__ __align__(16) float g_Wx[512 * NP];    // x-part weights (rows 0..511)
__device__ __align__(16) float g_Wh[512 * NP];    // h-part weights (rows 512..1023)
__device__ __align__(16) float g_ball[NP];        // packed biases (padded w/ zeros)
__device__ __align__(16) float g_preX[(size_t)T_STEPS * Bsz * NP];  // x@Wx+b, all steps
__device__ __align__(16) float g_pre0[Bsz * NP];  // recurrent partial (K 0..255)
__device__ __align__(16) float g_pre1[Bsz * NP];  // recurrent partial (K 256..511)
__device__ __align__(16) float g_hx[Bsz * Hh];
__device__ __align__(16) float g_cx[Bsz * Hh];

__device__ __forceinline__ float sigf(float x) { return 1.0f / (1.0f + expf(-x)); }

// ---------------------------------------------------------------------------
// Pack Wf|Wi|Wu|Wo|Wq rows into g_Wx (k<512) and g_Wh (k>=512), pad with 0.
// ---------------------------------------------------------------------------
__global__ void pack_kernel(const float* __restrict__ Wf, const float* __restrict__ Wi,
                            const float* __restrict__ Wu, const float* __restrict__ Wo,
                            const float* __restrict__ Wq,
                            const float* __restrict__ bf, const float* __restrict__ bi,
                            const float* __restrict__ bu, const float* __restrict__ bo,
                            const float* __restrict__ bq) {
    int stride = gridDim.x * blockDim.x;
    int idx = blockIdx.x * blockDim.x + threadIdx.x;

    for (int e = idx; e < 1024 * NP; e += stride) {
        int k = e / NP, n = e - k * NP;
        float v = 0.0f;
        if (n < 2048) {
            int g = n >> 9, c = n & 511;
            const float* W = (g == 0) ? Wf : (g == 1) ? Wi : (g == 2) ? Wu : Wo;
            v = W[k * 512 + c];
        } else if (n < NTOT) {
            v = Wq[k * NQv + (n - 2048)];
        }
        if (k < 512) g_Wx[k * NP + n] = v;
        else         g_Wh[(k - 512) * NP + n] = v;
    }
    for (int n = idx; n < NP; n += stride) {
        float v = 0.0f;
        if (n < 2048) {
            int g = n >> 9, c = n & 511;
            const float* bb = (g == 0) ? bf : (g == 1) ? bi : (g == 2) ? bu : bo;
            v = bb[c];
        } else if (n < NTOT) {
            v = bq[n - 2048];
        }
        g_ball[n] = v;
    }
    for (int e = idx; e < Bsz * Hh; e += stride) {
        g_hx[e] = 0.0f;
        g_cx[e] = 0.0f;
    }
}

// ---------------------------------------------------------------------------
// SGEMM: C = A(Mx512, lda=512) @ B(512xNP) [+ bias]
//   128x128 block tile, BK=16, 256 threads, 8x8 microtile,
//   register-prefetch double buffering. All dims exact multiples — no guards.
//   BIG=true : A=inputs chunk, B=g_Wx, C=g_preX, add bias. grid(17, M/128, 1)
//   BIG=false: A=g_hx, B=g_Wh, C=pre0/pre1 by z (split-K).  grid(17, 4, 2)
// ---------------------------------------------------------------------------
template<bool BIG>
__global__ __launch_bounds__(256, 2) void sgemm128(const float* __restrict__ Ain, int kLen) {
    __shared__ float As[16][132];
    __shared__ float Bs[16][128];

    const float* A = BIG ? Ain : g_hx;
    const float* B = BIG ? g_Wx : g_Wh;
    float* C = BIG ? g_preX : (blockIdx.z ? g_pre1 : g_pre0);

    const int tid = threadIdx.x;
    const int m0 = blockIdx.y * 128;
    const int n0 = blockIdx.x * 128;
    const int kStart = blockIdx.z * kLen;

    const int ar = tid >> 2, ac = (tid & 3) << 2;    // A: 64 rows/pass x 16 cols
    const int br = tid >> 5, bc = (tid & 31) << 2;   // B: 8 rows/pass x 128 cols

    const float* Ap = A + (size_t)(m0 + ar) * 512 + kStart + ac;
    const float* Bp = B + (size_t)(kStart + br) * NP + n0 + bc;

    float4 a0 = *(const float4*)Ap;
    float4 a1 = *(const float4*)(Ap + (size_t)64 * 512);
    float4 b0 = *(const float4*)Bp;
    float4 b1 = *(const float4*)(Bp + (size_t)8 * NP);

    float acc[8][8];
#pragma unroll
    for (int i = 0; i < 8; i++)
#pragma unroll
        for (int j = 0; j < 8; j++) acc[i][j] = 0.0f;

    const int tm = (tid >> 4) << 3;
    const int tn = (tid & 15) << 3;

    const int nIter = kLen >> 4;
    for (int it = 0; it < nIter; ++it) {
        As[ac + 0][ar] = a0.x; As[ac + 1][ar] = a0.y;
        As[ac + 2][ar] = a0.z; As[ac + 3][ar] = a0.w;
        As[ac + 0][ar + 64] = a1.x; As[ac + 1][ar + 64] = a1.y;
        As[ac + 2][ar + 64] = a1.z; As[ac + 3][ar + 64] = a1.w;
        *(float4*)&Bs[br][bc] = b0;
        *(float4*)&Bs[br + 8][bc] = b1;
        __syncthreads();

        if (it + 1 < nIter) {
            Ap += 16;
            Bp += (size_t)16 * NP;
            a0 = *(const float4*)Ap;
            a1 = *(const float4*)(Ap + (size_t)64 * 512);
            b0 = *(const float4*)Bp;
            b1 = *(const float4*)(Bp + (size_t)8 * NP);
        }

#pragma unroll
        for (int k = 0; k < 16; ++k) {
            float av[8], bv[8];
            *(float4*)(av)     = *(const float4*)&As[k][tm];
            *(float4*)(av + 4) = *(const float4*)&As[k][tm + 4];
            *(float4*)(bv)     = *(const float4*)&Bs[k][tn];
            *(float4*)(bv + 4) = *(const float4*)&Bs[k][tn + 4];
#pragma unroll
            for (int i = 0; i < 8; ++i)
#pragma unroll
                for (int j = 0; j < 8; ++j)
                    acc[i][j] = fmaf(av[i], bv[j], acc[i][j]);
        }
        __syncthreads();
    }

#pragma unroll
    for (int i = 0; i < 8; ++i) {
        float* crow = C + (size_t)(m0 + tm + i) * NP + n0 + tn;
        float r[8];
#pragma unroll
        for (int j = 0; j < 8; ++j) {
            r[j] = acc[i][j];
            if (BIG) r[j] += g_ball[n0 + tn + j];
        }
        *(float4*)(crow)     = *(const float4*)(r);
        *(float4*)(crow + 4) = *(const float4*)(r + 4);
    }
}

// ---------------------------------------------------------------------------
// Fused pointwise step: pre = preX[t] + pre0 + pre1, quantum cumprod layers,
// 8->H projections, gate blend, LSTM update. One block per batch row.
// ---------------------------------------------------------------------------
__global__ __launch_bounds__(512) void point_step(const float* __restrict__ Wqh,
                                                  const float* __restrict__ bqh,
                                                  const float* __restrict__ th_f,
                                                  const float* __restrict__ th_i,
                                                  const float* __restrict__ th_u,
                                                  const float* __restrict__ th_o,
                                                  float* __restrict__ out, int t) {
    int b = blockIdx.x;
    int h = threadIdx.x;

    const float* px = g_preX + (size_t)t * Bsz * NP + (size_t)b * NP;
    const float* p0 = g_pre0 + (size_t)b * NP;
    const float* p1 = g_pre1 + (size_t)b * NP;

    __shared__ float qv[4][NQv];   // cumprod(cos(q_in + theta_g)) per gate

    if (h < 4) {
        const float* th = (h == 0) ? th_f : (h == 1) ? th_i : (h == 2) ? th_u : th_o;
        float p = 1.0f;
#pragma unroll
        for (int w = 0; w < NQv; ++w) {
            float q = px[2048 + w] + p0[2048 + w] + p1[2048 + w];
            p *= cosf(q + th[w]);
            qv[h][w] = p;
        }
    }
    __syncthreads();

    float zf = bqh[h];
    float zi = zf, zu = zf, zo = zf;
#pragma unroll
    for (int w = 0; w < NQv; ++w) {
        float wq = Wqh[w * Hh + h];
        zf = fmaf(qv[0][w], wq, zf);
        zi = fmaf(qv[1][w], wq, zi);
        zu = fmaf(qv[2][w], wq, zu);
        zo = fmaf(qv[3][w], wq, zo);
    }

    float pf = px[h]        + p0[h]        + p1[h];
    float pi = px[512 + h]  + p0[512 + h]  + p1[512 + h];
    float pu = px[1024 + h] + p0[1024 + h] + p1[1024 + h];
    float po = px[1536 + h] + p0[1536 + h] + p1[1536 + h];

    const float A1 = 1.0f - ALPHA_C;
    float f  = ALPHA_C * sigf(pf)  + A1 * sigf(zf);
    float ii = ALPHA_C * sigf(pi)  + A1 * sigf(zi);
    float g  = ALPHA_C * tanhf(pu) + A1 * tanhf(zu);
    float o  = ALPHA_C * sigf(po)  + A1 * sigf(zo);

    size_t idx = (size_t)b * Hh + h;
    float c  = f * g_cx[idx] + ii * g;
    float hv = o * tanhf(c);
    g_cx[idx] = c;
    g_hx[idx] = hv;
    out[(size_t)t * (Bsz * Hh) + idx] = hv;
}

// ---------------------------------------------------------------------------
// Append final (hx, cx) after out[T,B,H].
// ---------------------------------------------------------------------------
__global__ void final_copy(float* __restrict__ dst) {
    int i = blockIdx.x * blockDim.x + threadIdx.x;
    if (i < Bsz * Hh) {
        dst[i] = g_hx[i];
        dst[Bsz * Hh + i] = g_cx[i];
    }
}

extern "C" void kernel_launch(void* const* d_in, const int* in_sizes, int n_in,
                              void* d_out, int out_size) {
    (void)in_sizes; (void)n_in; (void)out_size;
    const float* inputs = (const float*)d_in[0];
    const float* Wf  = (const float*)d_in[1];
    const float* bf  = (const float*)d_in[2];
    const float* Wi  = (const float*)d_in[3];
    const float* bi  = (const float*)d_in[4];
    const float* Wu  = (const float*)d_in[5];
    const float* bu  = (const float*)d_in[6];
    const float* Wo  = (const float*)d_in[7];
    const float* bo  = (const float*)d_in[8];
    const float* Wq  = (const float*)d_in[9];
    const float* bq  = (const float*)d_in[10];
    const float* Wqh = (const float*)d_in[11];
    const float* bqh = (const float*)d_in[12];
    const float* th_f = (const float*)d_in[13];
    const float* th_i = (const float*)d_in[14];
    const float* th_u = (const float*)d_in[15];
    const float* th_o = (const float*)d_in[16];
    float* out = (float*)d_out;

    pack_kernel<<<256, 256>>>(Wf, Wi, Wu, Wo, Wq, bf, bi, bu, bo, bq);

    // Precompute x-part for ALL timesteps: one big GEMM
    // M = T*B = 131072, K = 512, N = NP
    dim3 bigGrid(NP / 128, (T_STEPS * Bsz) / 128, 1);
    sgemm128<true><<<bigGrid, 256>>>(inputs, 512);

    // Sequential recurrence: per-step hx @ Wh with split-K=2
    dim3 recGrid(NP / 128, Bsz / 128, 2);
    for (int t = 0; t < T_STEPS; ++t) {
        sgemm128<false><<<recGrid, 256>>>(nullptr, 256);
        point_step<<<Bsz, Hh>>>(Wqh, bqh, th_f, th_i, th_u, th_o, out, t);
    }
    final_copy<<<(Bsz * Hh + 255) / 256, 256>>>(out + (size_t)T_STEPS * Bsz * Hh);
}

// round 9
// speedup vs baseline: 2.2653x; 1.5700x over previous
#include <cuda_runtime.h>
#include <cuda_bf16.h>
#include <math.h>
#include <stdint.h>

// Problem constants
#define T_STEPS 256
#define Bsz     512
#define Hh      512
#define NQv     8
#define NTOT    2056
#define NP      2176          // padded to 17*128
#define KV      1536          // virtual K: [hi@hi | hi@lo | lo@hi]
#define ALPHA_C 0.7f

// Scratch (no cudaMalloc allowed)
__device__ __align__(16) __nv_bfloat16 g_BX[KV * NP];   // packed x-weights [Whi;Wlo;Whi]
__device__ __align__(16) __nv_bfloat16 g_BH[KV * NP];   // packed h-weights [Whi;Wlo;Whi]
__device__ __align__(16) __nv_bfloat16 g_Xhi[(size_t)T_STEPS * Bsz * 512];
__device__ __align__(16) __nv_bfloat16 g_Xlo[(size_t)T_STEPS * Bsz * 512];
__device__ __align__(16) float g_ball[NP];
__device__ __align__(16) float g_preX[(size_t)T_STEPS * Bsz * NP];  // x@Wx+b, all steps
__device__ __align__(16) float g_pre[Bsz * NP];                      // recurrent hx@Wh
__device__ __align__(16) __nv_bfloat16 g_hxhi[Bsz * Hh];
__device__ __align__(16) __nv_bfloat16 g_hxlo[Bsz * Hh];
__device__ __align__(16) float g_hx[Bsz * Hh];
__device__ __align__(16) float g_cx[Bsz * Hh];

__device__ __forceinline__ float sigf(float x) { return 1.0f / (1.0f + expf(-x)); }

// ---------------------------------------------------------------------------
// Pack weights into split-bf16 B matrices. Virtual row kv in [0,1536):
//   region 0: hi(W row r), region 1: lo(W row r), region 2: hi(W row r)
// where r = kv & 511. g_BX uses original rows 0..511 (x part), g_BH uses
// rows 512..1023 (h part). Columns n<2048: Wf|Wi|Wu|Wo; 2048..2055: Wq; pad 0.
// ---------------------------------------------------------------------------
__global__ void pack_kernel(const float* __restrict__ Wf, const float* __restrict__ Wi,
                            const float* __restrict__ Wu, const float* __restrict__ Wo,
                            const float* __restrict__ Wq,
                            const float* __restrict__ bf, const float* __restrict__ bi,
                            const float* __restrict__ bu, const float* __restrict__ bo,
                            const float* __restrict__ bq) {
    int stride = gridDim.x * blockDim.x;
    int idx = blockIdx.x * blockDim.x + threadIdx.x;

    for (size_t e = idx; e < (size_t)KV * NP; e += stride) {
        int kv = (int)(e / NP), n = (int)(e - (size_t)kv * NP);
        int r = kv & 511;          // source row within the part
        int region = kv >> 9;      // 0:hi 1:lo 2:hi
        float wx = 0.0f, wh = 0.0f;
        if (n < 2048) {
            int g = n >> 9, c = n & 511;
            const float* W = (g == 0) ? Wf : (g == 1) ? Wi : (g == 2) ? Wu : Wo;
            wx = W[r * 512 + c];
            wh = W[(512 + r) * 512 + c];
        } else if (n < NTOT) {
            wx = Wq[r * NQv + (n - 2048)];
            wh = Wq[(512 + r) * NQv + (n - 2048)];
        }
        __nv_bfloat16 xh = __float2bfloat16_rn(wx);
        __nv_bfloat16 hh = __float2bfloat16_rn(wh);
        if (region == 1) {
            g_BX[e] = __float2bfloat16_rn(wx - __bfloat162float(xh));
            g_BH[e] = __float2bfloat16_rn(wh - __bfloat162float(hh));
        } else {
            g_BX[e] = xh;
            g_BH[e] = hh;
        }
    }
    for (int n = idx; n < NP; n += stride) {
        float v = 0.0f;
        if (n < 2048) {
            int g = n >> 9, c = n & 511;
            const float* bb = (g == 0) ? bf : (g == 1) ? bi : (g == 2) ? bu : bo;
            v = bb[c];
        } else if (n < NTOT) {
            v = bq[n - 2048];
        }
        g_ball[n] = v;
    }
    for (int e = idx; e < Bsz * Hh; e += stride) {
        g_hx[e] = 0.0f;
        g_cx[e] = 0.0f;
        g_hxhi[e] = __float2bfloat16_rn(0.0f);
        g_hxlo[e] = __float2bfloat16_rn(0.0f);
    }
}

// ---------------------------------------------------------------------------
// Split inputs into bf16 hi/lo.
// ---------------------------------------------------------------------------
__global__ void convert_x(const float* __restrict__ inputs) {
    size_t N = (size_t)T_STEPS * Bsz * 512;
    size_t stride = (size_t)gridDim.x * blockDim.x;
    for (size_t i = (size_t)blockIdx.x * blockDim.x + threadIdx.x; i < N; i += stride) {
        float v = inputs[i];
        __nv_bfloat16 h = __float2bfloat16_rn(v);
        g_Xhi[i] = h;
        g_Xlo[i] = __float2bfloat16_rn(v - __bfloat162float(h));
    }
}

// ---------------------------------------------------------------------------
// bf16 tensor-core GEMM with split-2 precision via virtual K = 1536.
//   C[M x NP] = A'[M x KV] @ B'[KV x NP]  (fp32 accumulate)
// A' columns: kv<512 -> Ahi[kv], kv<1024 -> Ahi[kv-512], else Alo[kv-1024].
// BM_ = 128 (BIG: A = g_Xhi/lo, B = g_BX, C = g_preX, +bias)
// BM_ = 64  (REC: A = g_hxhi/lo, B = g_BH, C = g_pre)
// 256 threads, BK = 32, ldmatrix + mma.sync.m16n8k16.
// ---------------------------------------------------------------------------
template<int BM_, bool BIG>
__global__ __launch_bounds__(256) void bgemm() {
    constexpr int BM    = BM_;
    constexpr int APASS = BM / 64;        // A gmem load passes
    constexpr int WM    = BM / 32;        // warps along m (4 or 2)
    constexpr int WN    = 8 / WM;         // warps along n (2 or 4)
    constexpr int WTN   = 128 / WN;       // warp n-tile (64 or 32)
    constexpr int NT_N  = WTN / 8;        // n8 tiles per warp (8 or 4)

    __shared__ __align__(16) __nv_bfloat16 As[BM][40];    // pad 8 -> stride 80B
    __shared__ __align__(16) __nv_bfloat16 Bs[32][136];   // pad 8 -> stride 272B

    const __nv_bfloat16* __restrict__ Ahi = BIG ? g_Xhi : g_hxhi;
    const __nv_bfloat16* __restrict__ Alo = BIG ? g_Xlo : g_hxlo;
    const __nv_bfloat16* __restrict__ Bm  = BIG ? g_BX  : g_BH;
    float* __restrict__ C = BIG ? g_preX : g_pre;

    const int tid  = threadIdx.x;
    const int lane = tid & 31;
    const int wid  = tid >> 5;
    const int m0   = blockIdx.y * BM;
    const int n0   = blockIdx.x * 128;

    // gmem load slots
    const int arow = tid >> 2;            // 0..63
    const int aseg = (tid & 3) << 3;      // bf16 col within slab
    const int brow = tid >> 4;            // 0..15
    const int bseg = (tid & 15) << 3;

    // warp tile coords
    const int wm = wid % WM;
    const int wn = wid / WM;

    // ldmatrix source coords
    const uint32_t As_base = (uint32_t)__cvta_generic_to_shared(&As[0][0]);
    const uint32_t Bs_base = (uint32_t)__cvta_generic_to_shared(&Bs[0][0]);
    const int a_r  = wm * 32 + (lane & 15);
    const int a_c  = (lane >> 4) << 3;
    const int b_r  = (lane & 15);
    const int b_c0 = wn * WTN + ((lane >> 4) << 3);

    float acc[2][NT_N][4];
#pragma unroll
    for (int i = 0; i < 2; ++i)
#pragma unroll
        for (int j = 0; j < NT_N; ++j)
#pragma unroll
            for (int k = 0; k < 4; ++k) acc[i][j][k] = 0.0f;

    // prefetch slab 0 (region 0 -> Ahi, col 0)
    uint4 apre[APASS], bpre[2];
#pragma unroll
    for (int p = 0; p < APASS; ++p)
        apre[p] = *(const uint4*)(Ahi + (size_t)(m0 + arow + p * 64) * 512 + aseg);
#pragma unroll
    for (int p = 0; p < 2; ++p)
        bpre[p] = *(const uint4*)(Bm + (size_t)(brow + p * 16) * NP + n0 + bseg);

    const int nIter = KV / 32;  // 48
    for (int it = 0; it < nIter; ++it) {
#pragma unroll
        for (int p = 0; p < APASS; ++p)
            *(uint4*)(&As[arow + p * 64][aseg]) = apre[p];
        *(uint4*)(&Bs[brow][bseg])      = bpre[0];
        *(uint4*)(&Bs[brow + 16][bseg]) = bpre[1];
        __syncthreads();

        if (it + 1 < nIter) {
            int kv = (it + 1) * 32;
            int acol = kv & 511;                       // works for all 3 regions
            const __nv_bfloat16* Ablk = (kv >= 1024) ? Alo : Ahi;
#pragma unroll
            for (int p = 0; p < APASS; ++p)
                apre[p] = *(const uint4*)(Ablk + (size_t)(m0 + arow + p * 64) * 512 + acol + aseg);
#pragma unroll
            for (int p = 0; p < 2; ++p)
                bpre[p] = *(const uint4*)(Bm + (size_t)(kv + brow + p * 16) * NP + n0 + bseg);
        }

#pragma unroll
        for (int kp = 0; kp < 2; ++kp) {
            uint32_t a[2][4];
#pragma unroll
            for (int mt = 0; mt < 2; ++mt) {
                uint32_t addr = As_base + (uint32_t)(((a_r + mt * 16) * 40 + a_c + kp * 16) * 2);
                asm volatile("ldmatrix.sync.aligned.m8n8.x4.shared.b16 {%0,%1,%2,%3}, [%4];"
                             : "=r"(a[mt][0]), "=r"(a[mt][1]), "=r"(a[mt][2]), "=r"(a[mt][3])
                             : "r"(addr));
            }
            uint32_t b[NT_N][2];
#pragma unroll
            for (int npair = 0; npair < NT_N / 2; ++npair) {
                uint32_t addr = Bs_base + (uint32_t)(((b_r + kp * 16) * 136 + b_c0 + npair * 16) * 2);
                asm volatile("ldmatrix.sync.aligned.m8n8.x4.trans.shared.b16 {%0,%1,%2,%3}, [%4];"
                             : "=r"(b[2 * npair][0]), "=r"(b[2 * npair][1]),
                               "=r"(b[2 * npair + 1][0]), "=r"(b[2 * npair + 1][1])
                             : "r"(addr));
            }
#pragma unroll
            for (int mt = 0; mt < 2; ++mt)
#pragma unroll
                for (int nt = 0; nt < NT_N; ++nt) {
                    asm volatile(
                        "mma.sync.aligned.m16n8k16.row.col.f32.bf16.bf16.f32 "
                        "{%0,%1,%2,%3}, {%4,%5,%6,%7}, {%8,%9}, {%0,%1,%2,%3};"
                        : "+f"(acc[mt][nt][0]), "+f"(acc[mt][nt][1]),
                          "+f"(acc[mt][nt][2]), "+f"(acc[mt][nt][3])
                        : "r"(a[mt][0]), "r"(a[mt][1]), "r"(a[mt][2]), "r"(a[mt][3]),
                          "r"(b[nt][0]), "r"(b[nt][1]));
                }
        }
        __syncthreads();
    }

    // Epilogue: d0,d1 -> row r, cols c..c+1 ; d2,d3 -> row r+8.
#pragma unroll
    for (int mt = 0; mt < 2; ++mt) {
        int r0 = m0 + wm * 32 + mt * 16 + (lane >> 2);
#pragma unroll
        for (int nt = 0; nt < NT_N; ++nt) {
            int c = n0 + wn * WTN + nt * 8 + (lane & 3) * 2;
            float2 v0 = make_float2(acc[mt][nt][0], acc[mt][nt][1]);
            float2 v1 = make_float2(acc[mt][nt][2], acc[mt][nt][3]);
            if (BIG) {
                float b0 = g_ball[c], b1 = g_ball[c + 1];
                v0.x += b0; v0.y += b1;
                v1.x += b0; v1.y += b1;
            }
            *(float2*)(C + (size_t)r0 * NP + c)       = v0;
            *(float2*)(C + (size_t)(r0 + 8) * NP + c) = v1;
        }
    }
}

// ---------------------------------------------------------------------------
// Fused pointwise step: pre = preX[t] + pre, quantum cumprod layers,
// 8->H projections, gate blend, LSTM update, bf16 hi/lo split of new hx.
// ---------------------------------------------------------------------------
__global__ __launch_bounds__(512) void point_step(const float* __restrict__ Wqh,
                                                  const float* __restrict__ bqh,
                                                  const float* __restrict__ th_f,
                                                  const float* __restrict__ th_i,
                                                  const float* __restrict__ th_u,
                                                  const float* __restrict__ th_o,
                                                  float* __restrict__ out, int t) {
    int b = blockIdx.x;
    int h = threadIdx.x;

    const float* px = g_preX + (size_t)t * Bsz * NP + (size_t)b * NP;
    const float* pr = g_pre + (size_t)b * NP;

    __shared__ float qv[4][NQv];

    if (h < 4) {
        const float* th = (h == 0) ? th_f : (h == 1) ? th_i : (h == 2) ? th_u : th_o;
        float p = 1.0f;
#pragma unroll
        for (int w = 0; w < NQv; ++w) {
            float q = px[2048 + w] + pr[2048 + w];
            p *= cosf(q + th[w]);
            qv[h][w] = p;
        }
    }
    __syncthreads();

    float zf = bqh[h];
    float zi = zf, zu = zf, zo = zf;
#pragma unroll
    for (int w = 0; w < NQv; ++w) {
        float wq = Wqh[w * Hh + h];
        zf = fmaf(qv[0][w], wq, zf);
        zi = fmaf(qv[1][w], wq, zi);
        zu = fmaf(qv[2][w], wq, zu);
        zo = fmaf(qv[3][w], wq, zo);
    }

    float pf = px[h]        + pr[h];
    float pi = px[512 + h]  + pr[512 + h];
    float pu = px[1024 + h] + pr[1024 + h];
    float po = px[1536 + h] + pr[1536 + h];

    const float A1 = 1.0f - ALPHA_C;
    float f  = ALPHA_C * sigf(pf)  + A1 * sigf(zf);
    float ii = ALPHA_C * sigf(pi)  + A1 * sigf(zi);
    float g  = ALPHA_C * tanhf(pu) + A1 * tanhf(zu);
    float o  = ALPHA_C * sigf(po)  + A1 * sigf(zo);

    size_t idx = (size_t)b * Hh + h;
    float c  = f * g_cx[idx] + ii * g;
    float hv = o * tanhf(c);
    g_cx[idx] = c;
    g_hx[idx] = hv;

    __nv_bfloat16 hh = __float2bfloat16_rn(hv);
    g_hxhi[idx] = hh;
    g_hxlo[idx] = __float2bfloat16_rn(hv - __bfloat162float(hh));

    out[(size_t)t * (Bsz * Hh) + idx] = hv;
}

// ---------------------------------------------------------------------------
// Append final (hx, cx) after out[T,B,H].
// ---------------------------------------------------------------------------
__global__ void final_copy(float* __restrict__ dst) {
    int i = blockIdx.x * blockDim.x + threadIdx.x;
    if (i < Bsz * Hh) {
        dst[i] = g_hx[i];
        dst[Bsz * Hh + i] = g_cx[i];
    }
}

extern "C" void kernel_launch(void* const* d_in, const int* in_sizes, int n_in,
                              void* d_out, int out_size) {
    (void)in_sizes; (void)n_in; (void)out_size;
    const float* inputs = (const float*)d_in[0];
    const float* Wf  = (const float*)d_in[1];
    const float* bf  = (const float*)d_in[2];
    const float* Wi  = (const float*)d_in[3];
    const float* bi  = (const float*)d_in[4];
    const float* Wu  = (const float*)d_in[5];
    const float* bu  = (const float*)d_in[6];
    const float* Wo  = (const float*)d_in[7];
    const float* bo  = (const float*)d_in[8];
    const float* Wq  = (const float*)d_in[9];
    const float* bq  = (const float*)d_in[10];
    const float* Wqh = (const float*)d_in[11];
    const float* bqh = (const float*)d_in[12];
    const float* th_f = (const float*)d_in[13];
    const float* th_i = (const float*)d_in[14];
    const float* th_u = (const float*)d_in[15];
    const float* th_o = (const float*)d_in[16];
    float* out = (float*)d_out;

    pack_kernel<<<512, 256>>>(Wf, Wi, Wu, Wo, Wq, bf, bi, bu, bo, bq);
    convert_x<<<4096, 256>>>(inputs);

    // Precompute x-part for ALL timesteps: M = 131072, virtual K = 1536, N = NP
    dim3 bigGrid(NP / 128, (T_STEPS * Bsz) / 128);
    bgemm<128, true><<<bigGrid, 256>>>();

    // Sequential recurrence: hx @ Wh (split-2 bf16), 17 x 8 = 136 blocks
    dim3 recGrid(NP / 128, Bsz / 64);
    for (int t = 0; t < T_STEPS; ++t) {
        bgemm<64, false><<<recGrid, 256>>>();
        point_step<<<Bsz, Hh>>>(Wqh, bqh, th_f, th_i, th_u, th_o, out, t);
    }
    final_copy<<<(Bsz * Hh + 255) / 256, 256>>>(out + (size_t)T_STEPS * Bsz * Hh);
}